// round 13
// baseline (speedup 1.0000x reference)
#include <cuda_runtime.h>
#include <cuda_fp16.h>
#include <math.h>

constexpr int N_NODES = 100000;
constexpr int N_HEDGE = 25000;
constexpr int N_EDGES = 600000;
constexpr int D       = 128;

// Fixed-capacity CSR. deg_n ~ Poisson(6): P(>=32) ~ 1e-15/node.
// deg_e ~ Poisson(24): P(>=72) ~ 1e-15/hedge. Overflow is clamped.
constexpr int CAP_N = 32;
constexpr int CAP_E = 72;
constexpr int DUMMY_NODE  = N_NODES;
constexpr int DUMMY_HEDGE = N_HEDGE;

constexpr int N_TILES_G  = 782;   // 32-row GEMM tiles over 25024 rows
constexpr int GEMM_BLKS  = 296;   // persistent, 2/SM

// ---------------------------------------------------------------------------
// Scratch
// ---------------------------------------------------------------------------
__device__ __half g_xh [(N_NODES + 1) * D];   // fp16 node features + zero row
__device__ __half g_m2h[(N_HEDGE + 1) * D];   // fp16 GEMM output + zero row
__device__ float  g_mf [25024 * D];           // fp32 hedge sums (GEMM input)
__device__ int   g_cur_n[N_NODES];
__device__ int   g_cur_e[N_HEDGE];
__device__ __align__(16) int g_adj_e[N_HEDGE * CAP_E + 8];
__device__ __align__(16) int g_adj_n[N_NODES * CAP_N + 8];

// ---------------------------------------------------------------------------
// Packed f32x2 helpers
// ---------------------------------------------------------------------------
__device__ __forceinline__ void fma2(unsigned long long& d, unsigned long long a,
                                     unsigned long long b) {
    asm("fma.rn.f32x2 %0, %1, %2, %0;" : "+l"(d) : "l"(a), "l"(b));
}
__device__ __forceinline__ unsigned long long pack2(float lo, float hi) {
    unsigned long long d;
    asm("mov.b64 %0, {%1, %2};" : "=l"(d) : "f"(lo), "f"(hi));
    return d;
}
__device__ __forceinline__ void unpack2(unsigned long long v, float& lo, float& hi) {
    asm("mov.b64 {%0, %1}, %2;" : "=f"(lo), "=f"(hi) : "l"(v));
}

// ---------------------------------------------------------------------------
// Preproc 1: fp16 convert of x + cursor init + zero rows
// ---------------------------------------------------------------------------
__global__ void init_kernel(const float* __restrict__ x) {
    int i = blockIdx.x * blockDim.x + threadIdx.x;
    if (i < N_NODES * D / 4) {
        float4 v = ((const float4*)x)[i];
        __half2 h0 = __floats2half2_rn(v.x, v.y);
        __half2 h1 = __floats2half2_rn(v.z, v.w);
        ((__half2*)g_xh)[i * 2]     = h0;
        ((__half2*)g_xh)[i * 2 + 1] = h1;
    }
    if (i < N_NODES) g_cur_n[i] = i * CAP_N;
    if (i < N_HEDGE) g_cur_e[i] = i * CAP_E;
    if (i < D) {
        g_xh [(size_t)N_NODES * D + i] = __float2half(0.f);
        g_m2h[(size_t)N_HEDGE * D + i] = __float2half(0.f);
    }
}

// ---------------------------------------------------------------------------
// Preproc 2: single-pass adjacency fill
// ---------------------------------------------------------------------------
__global__ void fill_adj_kernel(const int* __restrict__ node_idx,
                                const int* __restrict__ hedge_idx) {
    int e = blockIdx.x * blockDim.x + threadIdx.x;
    if (e >= N_EDGES) return;
    int nd = node_idx[e];
    int h  = hedge_idx[e];
    int p = atomicAdd(&g_cur_e[h], 1);
    if (p < h * CAP_E + CAP_E) g_adj_e[p] = nd;
    int q = atomicAdd(&g_cur_n[nd], 1);
    if (q < nd * CAP_N + CAP_N) g_adj_n[q] = h;
}

// ---------------------------------------------------------------------------
// Preproc 3: dummy-pad segments (node segments padded to the pair's deg4)
// ---------------------------------------------------------------------------
__global__ void pad_adj_kernel() {
    int i = blockIdx.x * blockDim.x + threadIdx.x;
    if (i < N_NODES) {
        int base  = i * CAP_N;
        int deg   = min(g_cur_n[i] - base, CAP_N);
        int pr    = i ^ 1;
        int degp  = min(g_cur_n[pr] - pr * CAP_N, CAP_N);
        int dmax4 = (max(deg, degp) + 3) & ~3;
        for (int j = deg; j < dmax4; j++) g_adj_n[base + j] = DUMMY_HEDGE;
    } else if (i < N_NODES + N_HEDGE) {
        int h    = i - N_NODES;
        int base = h * CAP_E;
        int deg  = min(g_cur_e[h] - base, CAP_E);
        int d4   = (deg + 3) & ~3;
        for (int j = deg; j < d4; j++) g_adj_e[base + j] = DUMMY_NODE;
    }
}

// ---------------------------------------------------------------------------
// Half-warp gather helpers
// ---------------------------------------------------------------------------
__device__ __forceinline__ void acc_row16(uint4 v, float2* a) {
    float2 f0 = __half22float2(*(const __half2*)&v.x);
    float2 f1 = __half22float2(*(const __half2*)&v.y);
    float2 f2 = __half22float2(*(const __half2*)&v.z);
    float2 f3 = __half22float2(*(const __half2*)&v.w);
    a[0].x += f0.x; a[0].y += f0.y;
    a[1].x += f1.x; a[1].y += f1.y;
    a[2].x += f2.x; a[2].y += f2.y;
    a[3].x += f3.x; a[3].y += f3.y;
}

__device__ __forceinline__ void gather16(const __half* __restrict__ src,
                                         const int* __restrict__ adj,
                                         int start, int deg, int l16,
                                         float2* a) {
    int deg4 = (deg + 3) & ~3;
    int j = 0;
    for (; j + 8 <= deg4; j += 8) {
        int4 iv0 = *(const int4*)(adj + start + j);
        int4 iv1 = *(const int4*)(adj + start + j + 4);
        uint4 r0 = ((const uint4*)(src + (size_t)iv0.x * D))[l16];
        uint4 r1 = ((const uint4*)(src + (size_t)iv0.y * D))[l16];
        uint4 r2 = ((const uint4*)(src + (size_t)iv0.z * D))[l16];
        uint4 r3 = ((const uint4*)(src + (size_t)iv0.w * D))[l16];
        uint4 r4 = ((const uint4*)(src + (size_t)iv1.x * D))[l16];
        uint4 r5 = ((const uint4*)(src + (size_t)iv1.y * D))[l16];
        uint4 r6 = ((const uint4*)(src + (size_t)iv1.z * D))[l16];
        uint4 r7 = ((const uint4*)(src + (size_t)iv1.w * D))[l16];
        acc_row16(r0, a); acc_row16(r1, a); acc_row16(r2, a); acc_row16(r3, a);
        acc_row16(r4, a); acc_row16(r5, a); acc_row16(r6, a); acc_row16(r7, a);
    }
    if (j < deg4) {
        int4 iv = *(const int4*)(adj + start + j);
        uint4 r0 = ((const uint4*)(src + (size_t)iv.x * D))[l16];
        uint4 r1 = ((const uint4*)(src + (size_t)iv.y * D))[l16];
        uint4 r2 = ((const uint4*)(src + (size_t)iv.z * D))[l16];
        uint4 r3 = ((const uint4*)(src + (size_t)iv.w * D))[l16];
        acc_row16(r0, a); acc_row16(r1, a); acc_row16(r2, a); acc_row16(r3, a);
    }
}

// ---------------------------------------------------------------------------
// Hyperedge gather: 1 hedge per half-warp, high occupancy, fp32 output.
// ---------------------------------------------------------------------------
__global__ void __launch_bounds__(256)
hedge_gather_kernel(const __half* __restrict__ xh, float* __restrict__ mf) {
    int lane = threadIdx.x & 31;
    int l16  = lane & 15;
    int h    = ((blockIdx.x * blockDim.x + threadIdx.x) >> 4);
    if (h >= N_HEDGE) return;

    int base = h * CAP_E;
    int deg  = min(g_cur_e[h] - base, CAP_E);

    float2 a[4] = {{0.f,0.f},{0.f,0.f},{0.f,0.f},{0.f,0.f}};
    gather16(xh, g_adj_e, base, deg, l16, a);

    float s = deg > 0 ? 1.0f / (float)deg : 0.0f;
    float4* row = (float4*)(mf + (size_t)h * D);
    row[2 * l16]     = make_float4(a[0].x * s, a[0].y * s, a[1].x * s, a[1].y * s);
    row[2 * l16 + 1] = make_float4(a[2].x * s, a[2].y * s, a[3].x * s, a[3].y * s);
}

// ---------------------------------------------------------------------------
// Dense GEMM: m2h[r,:] = fp16(mf[r,:] @ W). Persistent 296 blocks, W in smem
// loaded once, static-strided 32-row tiles. f32x2 FMA.
// ---------------------------------------------------------------------------
__global__ void __launch_bounds__(256)
gemm_kernel(const float* __restrict__ A, const float* __restrict__ W,
            __half* __restrict__ m2h) {
    extern __shared__ float sm[];
    float* Ws = sm;              // 128*128 = 64KB
    float* Xs = sm + 128 * 128;  // 32*128  = 16KB
    int t  = threadIdx.x;
    int tx = t & 31;   // col group: floats [4*tx .. 4*tx+3]
    int ty = t >> 5;   // 0..7; rows ty, ty+8, ty+16, ty+24

    for (int i = t; i < 128 * 128 / 4; i += 256)
        ((float4*)Ws)[i] = ((const float4*)W)[i];
    __syncthreads();

    for (int tile = blockIdx.x; tile < N_TILES_G; tile += GEMM_BLKS) {
        int row0 = tile * 32;

        // Load A tile (coalesced; rows >= N_HEDGE are garbage but unused)
        const float4* asrc = (const float4*)(A + (size_t)row0 * D);
        #pragma unroll
        for (int i = 0; i < 4; i++)
            ((float4*)Xs)[t + i * 256] = asrc[t + i * 256];
        __syncthreads();

        unsigned long long acc01[4], acc23[4];
        #pragma unroll
        for (int r = 0; r < 4; r++) { acc01[r] = 0ull; acc23[r] = 0ull; }

        #pragma unroll 4
        for (int k = 0; k < 128; k++) {
            ulonglong2 wv = ((const ulonglong2*)(Ws + k * 128))[tx];
            #pragma unroll
            for (int r = 0; r < 4; r++) {
                float a = Xs[(ty + r * 8) * 128 + k];
                unsigned long long aa = pack2(a, a);
                fma2(acc01[r], aa, wv.x);
                fma2(acc23[r], aa, wv.y);
            }
        }

        #pragma unroll
        for (int r = 0; r < 4; r++) {
            int gr = row0 + ty + r * 8;
            if (gr < N_HEDGE) {
                float c0, c1, c2, c3;
                unpack2(acc01[r], c0, c1);
                unpack2(acc23[r], c2, c3);
                __half2 h0 = __floats2half2_rn(c0, c1);
                __half2 h1 = __floats2half2_rn(c2, c3);
                uint2 pv;
                pv.x = *(unsigned int*)&h0;
                pv.y = *(unsigned int*)&h1;
                ((uint2*)(m2h + (size_t)gr * D))[tx] = pv;
            }
        }
        __syncthreads();   // protect Xs before next tile load
    }
}

// ---------------------------------------------------------------------------
// Node stage: two nodes per half-warp, interleaved loads.
// ---------------------------------------------------------------------------
__device__ __forceinline__ float elu_f(float v) {
    return v > 0.0f ? v : expm1f(v);
}

template <bool LAST>
__global__ void __launch_bounds__(256)
node_gather_kernel(const __half* __restrict__ m2h, const float* __restrict__ bias,
                   float* __restrict__ out) {
    int lane = threadIdx.x & 31;
    int l16  = lane & 15;
    int pid  = ((blockIdx.x * blockDim.x + threadIdx.x) >> 4);
    if (pid >= N_NODES / 2) return;
    int n0 = pid * 2;
    int n1 = n0 + 1;

    int base0 = n0 * CAP_N;
    int base1 = n1 * CAP_N;
    int deg0  = min(g_cur_n[n0] - base0, CAP_N);
    int deg1  = min(g_cur_n[n1] - base1, CAP_N);
    int dmax4 = (max(deg0, deg1) + 3) & ~3;

    float2 a0[4] = {{0.f,0.f},{0.f,0.f},{0.f,0.f},{0.f,0.f}};
    float2 a1[4] = {{0.f,0.f},{0.f,0.f},{0.f,0.f},{0.f,0.f}};

    for (int j = 0; j < dmax4; j += 4) {
        int4 iv0 = *(const int4*)(g_adj_n + base0 + j);
        int4 iv1 = *(const int4*)(g_adj_n + base1 + j);
        uint4 r00 = ((const uint4*)(m2h + (size_t)iv0.x * D))[l16];
        uint4 r01 = ((const uint4*)(m2h + (size_t)iv0.y * D))[l16];
        uint4 r02 = ((const uint4*)(m2h + (size_t)iv0.z * D))[l16];
        uint4 r03 = ((const uint4*)(m2h + (size_t)iv0.w * D))[l16];
        uint4 r10 = ((const uint4*)(m2h + (size_t)iv1.x * D))[l16];
        uint4 r11 = ((const uint4*)(m2h + (size_t)iv1.y * D))[l16];
        uint4 r12 = ((const uint4*)(m2h + (size_t)iv1.z * D))[l16];
        uint4 r13 = ((const uint4*)(m2h + (size_t)iv1.w * D))[l16];
        acc_row16(r00, a0); acc_row16(r01, a0);
        acc_row16(r02, a0); acc_row16(r03, a0);
        acc_row16(r10, a1); acc_row16(r11, a1);
        acc_row16(r12, a1); acc_row16(r13, a1);
    }

    float4 b0 = ((const float4*)bias)[2 * l16];
    float4 b1 = ((const float4*)bias)[2 * l16 + 1];

    #pragma unroll
    for (int r = 0; r < 2; r++) {
        float2* a  = r ? a1 : a0;
        int     gw = r ? n1 : n0;
        int    deg = r ? deg1 : deg0;
        float s = deg > 0 ? 1.0f / (float)deg : 0.0f;
        float v0 = elu_f(fmaf(a[0].x, s, b0.x));
        float v1 = elu_f(fmaf(a[0].y, s, b0.y));
        float v2 = elu_f(fmaf(a[1].x, s, b0.z));
        float v3 = elu_f(fmaf(a[1].y, s, b0.w));
        float v4 = elu_f(fmaf(a[2].x, s, b1.x));
        float v5 = elu_f(fmaf(a[2].y, s, b1.y));
        float v6 = elu_f(fmaf(a[3].x, s, b1.z));
        float v7 = elu_f(fmaf(a[3].y, s, b1.w));
        if (LAST) {
            float4* orow = (float4*)(out + (size_t)gw * D);
            orow[2 * l16]     = make_float4(v0, v1, v2, v3);
            orow[2 * l16 + 1] = make_float4(v4, v5, v6, v7);
        } else {
            __half2 h0 = __floats2half2_rn(v0, v1);
            __half2 h1 = __floats2half2_rn(v2, v3);
            __half2 h2 = __floats2half2_rn(v4, v5);
            __half2 h3 = __floats2half2_rn(v6, v7);
            uint4 pv;
            pv.x = *(unsigned int*)&h0;
            pv.y = *(unsigned int*)&h1;
            pv.z = *(unsigned int*)&h2;
            pv.w = *(unsigned int*)&h3;
            ((uint4*)(g_xh + (size_t)gw * D))[l16] = pv;
        }
    }
}

// ---------------------------------------------------------------------------
// Launch
// ---------------------------------------------------------------------------
extern "C" void kernel_launch(void* const* d_in, const int* in_sizes, int n_in,
                              void* d_out, int out_size) {
    const float* x  = (const float*)d_in[0];
    const float* W1 = (const float*)d_in[1];
    const float* b1 = (const float*)d_in[2];
    const float* W2 = (const float*)d_in[3];
    const float* b2 = (const float*)d_in[4];
    const float* W3 = (const float*)d_in[5];
    const float* b3 = (const float*)d_in[6];
    const int* node_idx  = (const int*)d_in[7];
    const int* hedge_idx = (const int*)d_in[8];
    float* out = (float*)d_out;

    __half *p_xh, *p_m2h;
    float  *p_mf;
    cudaGetSymbolAddress((void**)&p_xh,  g_xh);
    cudaGetSymbolAddress((void**)&p_m2h, g_m2h);
    cudaGetSymbolAddress((void**)&p_mf,  g_mf);

    const int GEMM_SMEM = (128 * 128 + 32 * 128) * (int)sizeof(float);  // 80KB
    cudaFuncSetAttribute(gemm_kernel,
                         cudaFuncAttributeMaxDynamicSharedMemorySize, GEMM_SMEM);

    // Preproc: 3 launches
    init_kernel<<<(N_NODES * D / 4 + 255) / 256, 256>>>(x);
    fill_adj_kernel<<<(N_EDGES + 255) / 256, 256>>>(node_idx, hedge_idx);
    pad_adj_kernel<<<(N_NODES + N_HEDGE + 255) / 256, 256>>>();

    const int HGB = (N_HEDGE * 16 + 255) / 256;       // 1563
    const int NGB = (N_NODES / 2 * 16 + 255) / 256;   // 3125

    hedge_gather_kernel<<<HGB, 256>>>(p_xh, p_mf);
    gemm_kernel<<<GEMM_BLKS, 256, GEMM_SMEM>>>(p_mf, W1, p_m2h);
    node_gather_kernel<false><<<NGB, 256>>>(p_m2h, b1, nullptr);

    hedge_gather_kernel<<<HGB, 256>>>(p_xh, p_mf);
    gemm_kernel<<<GEMM_BLKS, 256, GEMM_SMEM>>>(p_mf, W2, p_m2h);
    node_gather_kernel<false><<<NGB, 256>>>(p_m2h, b2, nullptr);

    hedge_gather_kernel<<<HGB, 256>>>(p_xh, p_mf);
    gemm_kernel<<<GEMM_BLKS, 256, GEMM_SMEM>>>(p_mf, W3, p_m2h);
    node_gather_kernel<true><<<NGB, 256>>>(p_m2h, b3, out);
}

// round 15
// speedup vs baseline: 1.2941x; 1.2941x over previous
#include <cuda_runtime.h>
#include <cuda_fp16.h>
#include <math.h>
#include <cstdint>

constexpr int N_NODES = 100000;
constexpr int N_HEDGE = 25000;
constexpr int N_EDGES = 600000;
constexpr int D       = 128;

// Fixed-capacity CSR (clamped; overflow prob ~1e-14).
constexpr int CAP_N = 32;
constexpr int CAP_E = 72;
constexpr int DUMMY_NODE  = N_NODES;
constexpr int DUMMY_HEDGE = N_HEDGE;

constexpr int ROWS_PAD = 25024;            // 391 * 64
constexpr int GEMM_TILES = ROWS_PAD / 64;  // 391

// ---------------------------------------------------------------------------
// Scratch
// ---------------------------------------------------------------------------
__device__ __half g_xh [(N_NODES + 1) * D];   // fp16 node features + zero row
__device__ __half g_m2h[(N_HEDGE + 1) * D];   // fp16 GEMM output + zero row
__device__ __half g_mfh[ROWS_PAD * D];        // fp16 hedge sums (GEMM A)
__device__ int   g_cur_n[N_NODES];
__device__ int   g_cur_e[N_HEDGE];
__device__ __align__(16) int g_adj_e[N_HEDGE * CAP_E + 8];
__device__ __align__(16) int g_adj_n[N_NODES * CAP_N + 8];

// ---------------------------------------------------------------------------
// Preproc 1: fp16 convert of x + cursor init + zero rows
// ---------------------------------------------------------------------------
__global__ void init_kernel(const float* __restrict__ x) {
    int i = blockIdx.x * blockDim.x + threadIdx.x;
    if (i < N_NODES * D / 4) {
        float4 v = ((const float4*)x)[i];
        __half2 h0 = __floats2half2_rn(v.x, v.y);
        __half2 h1 = __floats2half2_rn(v.z, v.w);
        ((__half2*)g_xh)[i * 2]     = h0;
        ((__half2*)g_xh)[i * 2 + 1] = h1;
    }
    if (i < N_NODES) g_cur_n[i] = i * CAP_N;
    if (i < N_HEDGE) g_cur_e[i] = i * CAP_E;
    if (i < D) {
        g_xh [(size_t)N_NODES * D + i] = __float2half(0.f);
        g_m2h[(size_t)N_HEDGE * D + i] = __float2half(0.f);
    }
}

// ---------------------------------------------------------------------------
// Preproc 2: single-pass adjacency fill
// ---------------------------------------------------------------------------
__global__ void fill_adj_kernel(const int* __restrict__ node_idx,
                                const int* __restrict__ hedge_idx) {
    int e = blockIdx.x * blockDim.x + threadIdx.x;
    if (e >= N_EDGES) return;
    int nd = node_idx[e];
    int h  = hedge_idx[e];
    int p = atomicAdd(&g_cur_e[h], 1);
    if (p < h * CAP_E + CAP_E) g_adj_e[p] = nd;
    int q = atomicAdd(&g_cur_n[nd], 1);
    if (q < nd * CAP_N + CAP_N) g_adj_n[q] = h;
}

// ---------------------------------------------------------------------------
// Preproc 3: dummy-pad segments (node segments padded to the pair's deg4)
// ---------------------------------------------------------------------------
__global__ void pad_adj_kernel() {
    int i = blockIdx.x * blockDim.x + threadIdx.x;
    if (i < N_NODES) {
        int base  = i * CAP_N;
        int deg   = min(g_cur_n[i] - base, CAP_N);
        int pr    = i ^ 1;
        int degp  = min(g_cur_n[pr] - pr * CAP_N, CAP_N);
        int dmax4 = (max(deg, degp) + 3) & ~3;
        for (int j = deg; j < dmax4; j++) g_adj_n[base + j] = DUMMY_HEDGE;
    } else if (i < N_NODES + N_HEDGE) {
        int h    = i - N_NODES;
        int base = h * CAP_E;
        int deg  = min(g_cur_e[h] - base, CAP_E);
        int d4   = (deg + 3) & ~3;
        for (int j = deg; j < d4; j++) g_adj_e[base + j] = DUMMY_NODE;
    }
}

// ---------------------------------------------------------------------------
// Half-warp gather helpers (fp16 rows, fp32 accumulation)
// ---------------------------------------------------------------------------
__device__ __forceinline__ void acc_row16(uint4 v, float2* a) {
    float2 f0 = __half22float2(*(const __half2*)&v.x);
    float2 f1 = __half22float2(*(const __half2*)&v.y);
    float2 f2 = __half22float2(*(const __half2*)&v.z);
    float2 f3 = __half22float2(*(const __half2*)&v.w);
    a[0].x += f0.x; a[0].y += f0.y;
    a[1].x += f1.x; a[1].y += f1.y;
    a[2].x += f2.x; a[2].y += f2.y;
    a[3].x += f3.x; a[3].y += f3.y;
}

__device__ __forceinline__ void gather16(const __half* __restrict__ src,
                                         const int* __restrict__ adj,
                                         int start, int deg, int l16,
                                         float2* a) {
    int deg4 = (deg + 3) & ~3;
    int j = 0;
    for (; j + 8 <= deg4; j += 8) {
        int4 iv0 = *(const int4*)(adj + start + j);
        int4 iv1 = *(const int4*)(adj + start + j + 4);
        uint4 r0 = ((const uint4*)(src + (size_t)iv0.x * D))[l16];
        uint4 r1 = ((const uint4*)(src + (size_t)iv0.y * D))[l16];
        uint4 r2 = ((const uint4*)(src + (size_t)iv0.z * D))[l16];
        uint4 r3 = ((const uint4*)(src + (size_t)iv0.w * D))[l16];
        uint4 r4 = ((const uint4*)(src + (size_t)iv1.x * D))[l16];
        uint4 r5 = ((const uint4*)(src + (size_t)iv1.y * D))[l16];
        uint4 r6 = ((const uint4*)(src + (size_t)iv1.z * D))[l16];
        uint4 r7 = ((const uint4*)(src + (size_t)iv1.w * D))[l16];
        acc_row16(r0, a); acc_row16(r1, a); acc_row16(r2, a); acc_row16(r3, a);
        acc_row16(r4, a); acc_row16(r5, a); acc_row16(r6, a); acc_row16(r7, a);
    }
    if (j < deg4) {
        int4 iv = *(const int4*)(adj + start + j);
        uint4 r0 = ((const uint4*)(src + (size_t)iv.x * D))[l16];
        uint4 r1 = ((const uint4*)(src + (size_t)iv.y * D))[l16];
        uint4 r2 = ((const uint4*)(src + (size_t)iv.z * D))[l16];
        uint4 r3 = ((const uint4*)(src + (size_t)iv.w * D))[l16];
        acc_row16(r0, a); acc_row16(r1, a); acc_row16(r2, a); acc_row16(r3, a);
    }
}

// ---------------------------------------------------------------------------
// Hyperedge gather: 1 hedge per half-warp, fp16 output row.
// ---------------------------------------------------------------------------
__global__ void __launch_bounds__(256)
hedge_gather_kernel(const __half* __restrict__ xh, __half* __restrict__ mfh) {
    int lane = threadIdx.x & 31;
    int l16  = lane & 15;
    int h    = ((blockIdx.x * blockDim.x + threadIdx.x) >> 4);
    if (h >= N_HEDGE) return;

    int base = h * CAP_E;
    int deg  = min(g_cur_e[h] - base, CAP_E);

    float2 a[4] = {{0.f,0.f},{0.f,0.f},{0.f,0.f},{0.f,0.f}};
    gather16(xh, g_adj_e, base, deg, l16, a);

    float s = deg > 0 ? 1.0f / (float)deg : 0.0f;
    __half2 h0 = __floats2half2_rn(a[0].x * s, a[0].y * s);
    __half2 h1 = __floats2half2_rn(a[1].x * s, a[1].y * s);
    __half2 h2 = __floats2half2_rn(a[2].x * s, a[2].y * s);
    __half2 h3 = __floats2half2_rn(a[3].x * s, a[3].y * s);
    uint4 pv;
    pv.x = *(unsigned int*)&h0;
    pv.y = *(unsigned int*)&h1;
    pv.z = *(unsigned int*)&h2;
    pv.w = *(unsigned int*)&h3;
    ((uint4*)(mfh + (size_t)h * D))[l16] = pv;
}

// ---------------------------------------------------------------------------
// HMMA GEMM: m2h[r,:] = fp16( mfh[r,:] @ W ),   64-row tile per block.
// 512 threads = 16 warps in a 4(m) x 4(n) grid; each warp does m16 x n32.
// Smem layout (fp16, 256B rows, 16B slots, slot ^ (row&15) swizzle):
//   Ws: W as fp16, row-major [k][n]  (32 KB)
//   Xs: A tile    [row][k]           (16 KB)
// ---------------------------------------------------------------------------
__device__ __forceinline__ uint32_t s2u(const void* p) {
    return (uint32_t)__cvta_generic_to_shared(p);
}

__global__ void __launch_bounds__(512)
gemm_hmma_kernel(const __half* __restrict__ A, const float* __restrict__ W,
                 __half* __restrict__ m2h) {
    extern __shared__ __half smh[];
    __half* Ws = smh;              // 128 rows x 128 halfs
    __half* Xs = smh + 128 * 128;  // 64 rows x 128 halfs
    int t    = threadIdx.x;
    int lane = t & 31;
    int wid  = t >> 5;           // 0..15
    int wm   = wid >> 2;         // warp row group (16 rows)
    int wn   = wid & 3;          // warp col group (32 cols)

    int row0 = blockIdx.x * 64;

    // Stage W: fp32 gmem -> fp16 swizzled smem. 2048 slots, 4 per thread.
    #pragma unroll
    for (int it = 0; it < 4; it++) {
        int ls   = t + it * 512;          // 0..2047
        int row  = ls >> 4;
        int c16  = ls & 15;
        int phys = c16 ^ (row & 15);
        float4 f0 = ((const float4*)W)[row * 32 + c16 * 2];
        float4 f1 = ((const float4*)W)[row * 32 + c16 * 2 + 1];
        __half2 q0 = __floats2half2_rn(f0.x, f0.y);
        __half2 q1 = __floats2half2_rn(f0.z, f0.w);
        __half2 q2 = __floats2half2_rn(f1.x, f1.y);
        __half2 q3 = __floats2half2_rn(f1.z, f1.w);
        uint4 pv;
        pv.x = *(unsigned int*)&q0;
        pv.y = *(unsigned int*)&q1;
        pv.z = *(unsigned int*)&q2;
        pv.w = *(unsigned int*)&q3;
        ((uint4*)Ws)[row * 16 + phys] = pv;
    }

    // Stage A tile: 1024 slots, 2 per thread.
    #pragma unroll
    for (int it = 0; it < 2; it++) {
        int ls   = t + it * 512;          // 0..1023
        int row  = ls >> 4;
        int c16  = ls & 15;
        int phys = c16 ^ (row & 15);
        uint4 pv = ((const uint4*)(A + (size_t)(row0 + row) * D))[c16];
        ((uint4*)Xs)[row * 16 + phys] = pv;
    }
    __syncthreads();

    // Accumulators: 4 n8 tiles x 4 f32
    float c[4][4];
    #pragma unroll
    for (int j = 0; j < 4; j++)
        #pragma unroll
        for (int q = 0; q < 4; q++) c[j][q] = 0.f;

    int g  = lane >> 3;    // 0..3 (ldmatrix matrix group)
    int r8 = lane & 7;

    // A address components (row fixed per lane)
    int arow = wm * 16 + r8 + (g & 1) * 8;
    uint32_t abase = s2u(Xs) + arow * 256;
    // B address components
    int brow_off = r8 + (g & 1) * 8;      // + 16*s
    int bq = g >> 1;                       // 0/1 within each x4

    #pragma unroll
    for (int s = 0; s < 8; s++) {
        // A fragment (m16 x k16)
        uint32_t a0, a1, a2, a3;
        {
            int slot = 2 * s + (g >> 1);
            uint32_t addr = abase + ((slot ^ (arow & 15)) << 4);
            asm volatile("ldmatrix.sync.aligned.m8n8.x4.shared.b16 {%0,%1,%2,%3}, [%4];"
                         : "=r"(a0), "=r"(a1), "=r"(a2), "=r"(a3) : "r"(addr));
        }
        // B fragments: two x4.trans, each covers two n8 tiles
        uint32_t b[4][2];
        #pragma unroll
        for (int half = 0; half < 2; half++) {
            int brow = 16 * s + brow_off;
            int slot = wn * 4 + half * 2 + bq;
            uint32_t addr = s2u(Ws) + brow * 256 + ((slot ^ (brow & 15)) << 4);
            uint32_t d0, d1, d2, d3;
            asm volatile("ldmatrix.sync.aligned.m8n8.x4.trans.shared.b16 {%0,%1,%2,%3}, [%4];"
                         : "=r"(d0), "=r"(d1), "=r"(d2), "=r"(d3) : "r"(addr));
            b[half * 2][0]     = d0;
            b[half * 2][1]     = d1;
            b[half * 2 + 1][0] = d2;
            b[half * 2 + 1][1] = d3;
        }
        // 4 mma per k-step
        #pragma unroll
        for (int j = 0; j < 4; j++) {
            asm volatile(
                "mma.sync.aligned.m16n8k16.row.col.f32.f16.f16.f32 "
                "{%0,%1,%2,%3}, {%4,%5,%6,%7}, {%8,%9}, {%0,%1,%2,%3};"
                : "+f"(c[j][0]), "+f"(c[j][1]), "+f"(c[j][2]), "+f"(c[j][3])
                : "r"(a0), "r"(a1), "r"(a2), "r"(a3),
                  "r"(b[j][0]), "r"(b[j][1]));
        }
    }

    // Epilogue: C -> fp16 gmem.
    int tg  = lane >> 2;
    int tig = lane & 3;
    int r_lo = row0 + wm * 16 + tg;
    int r_hi = r_lo + 8;
    int col  = wn * 32 + tig * 2;
    #pragma unroll
    for (int j = 0; j < 4; j++) {
        int cc = col + j * 8;
        if (r_lo < N_HEDGE) {
            __half2 v = __floats2half2_rn(c[j][0], c[j][1]);
            *(__half2*)(m2h + (size_t)r_lo * D + cc) = v;
        }
        if (r_hi < N_HEDGE) {
            __half2 v = __floats2half2_rn(c[j][2], c[j][3]);
            *(__half2*)(m2h + (size_t)r_hi * D + cc) = v;
        }
    }
}

// ---------------------------------------------------------------------------
// Node stage: two nodes per half-warp, interleaved loads.
// ---------------------------------------------------------------------------
__device__ __forceinline__ float elu_f(float v) {
    return v > 0.0f ? v : expm1f(v);
}

template <bool LAST>
__global__ void __launch_bounds__(256)
node_gather_kernel(const __half* __restrict__ m2h, const float* __restrict__ bias,
                   float* __restrict__ out) {
    int lane = threadIdx.x & 31;
    int l16  = lane & 15;
    int pid  = ((blockIdx.x * blockDim.x + threadIdx.x) >> 4);
    if (pid >= N_NODES / 2) return;
    int n0 = pid * 2;
    int n1 = n0 + 1;

    int base0 = n0 * CAP_N;
    int base1 = n1 * CAP_N;
    int deg0  = min(g_cur_n[n0] - base0, CAP_N);
    int deg1  = min(g_cur_n[n1] - base1, CAP_N);
    int dmax4 = (max(deg0, deg1) + 3) & ~3;

    float2 a0[4] = {{0.f,0.f},{0.f,0.f},{0.f,0.f},{0.f,0.f}};
    float2 a1[4] = {{0.f,0.f},{0.f,0.f},{0.f,0.f},{0.f,0.f}};

    for (int j = 0; j < dmax4; j += 4) {
        int4 iv0 = *(const int4*)(g_adj_n + base0 + j);
        int4 iv1 = *(const int4*)(g_adj_n + base1 + j);
        uint4 r00 = ((const uint4*)(m2h + (size_t)iv0.x * D))[l16];
        uint4 r01 = ((const uint4*)(m2h + (size_t)iv0.y * D))[l16];
        uint4 r02 = ((const uint4*)(m2h + (size_t)iv0.z * D))[l16];
        uint4 r03 = ((const uint4*)(m2h + (size_t)iv0.w * D))[l16];
        uint4 r10 = ((const uint4*)(m2h + (size_t)iv1.x * D))[l16];
        uint4 r11 = ((const uint4*)(m2h + (size_t)iv1.y * D))[l16];
        uint4 r12 = ((const uint4*)(m2h + (size_t)iv1.z * D))[l16];
        uint4 r13 = ((const uint4*)(m2h + (size_t)iv1.w * D))[l16];
        acc_row16(r00, a0); acc_row16(r01, a0);
        acc_row16(r02, a0); acc_row16(r03, a0);
        acc_row16(r10, a1); acc_row16(r11, a1);
        acc_row16(r12, a1); acc_row16(r13, a1);
    }

    float4 b0 = ((const float4*)bias)[2 * l16];
    float4 b1 = ((const float4*)bias)[2 * l16 + 1];

    #pragma unroll
    for (int r = 0; r < 2; r++) {
        float2* a  = r ? a1 : a0;
        int     gw = r ? n1 : n0;
        int    deg = r ? deg1 : deg0;
        float s = deg > 0 ? 1.0f / (float)deg : 0.0f;
        float v0 = elu_f(fmaf(a[0].x, s, b0.x));
        float v1 = elu_f(fmaf(a[0].y, s, b0.y));
        float v2 = elu_f(fmaf(a[1].x, s, b0.z));
        float v3 = elu_f(fmaf(a[1].y, s, b0.w));
        float v4 = elu_f(fmaf(a[2].x, s, b1.x));
        float v5 = elu_f(fmaf(a[2].y, s, b1.y));
        float v6 = elu_f(fmaf(a[3].x, s, b1.z));
        float v7 = elu_f(fmaf(a[3].y, s, b1.w));
        if (LAST) {
            float4* orow = (float4*)(out + (size_t)gw * D);
            orow[2 * l16]     = make_float4(v0, v1, v2, v3);
            orow[2 * l16 + 1] = make_float4(v4, v5, v6, v7);
        } else {
            __half2 h0 = __floats2half2_rn(v0, v1);
            __half2 h1 = __floats2half2_rn(v2, v3);
            __half2 h2 = __floats2half2_rn(v4, v5);
            __half2 h3 = __floats2half2_rn(v6, v7);
            uint4 pv;
            pv.x = *(unsigned int*)&h0;
            pv.y = *(unsigned int*)&h1;
            pv.z = *(unsigned int*)&h2;
            pv.w = *(unsigned int*)&h3;
            ((uint4*)(g_xh + (size_t)gw * D))[l16] = pv;
        }
    }
}

// ---------------------------------------------------------------------------
// Launch
// ---------------------------------------------------------------------------
extern "C" void kernel_launch(void* const* d_in, const int* in_sizes, int n_in,
                              void* d_out, int out_size) {
    const float* x  = (const float*)d_in[0];
    const float* W1 = (const float*)d_in[1];
    const float* b1 = (const float*)d_in[2];
    const float* W2 = (const float*)d_in[3];
    const float* b2 = (const float*)d_in[4];
    const float* W3 = (const float*)d_in[5];
    const float* b3 = (const float*)d_in[6];
    const int* node_idx  = (const int*)d_in[7];
    const int* hedge_idx = (const int*)d_in[8];
    float* out = (float*)d_out;

    __half *p_xh, *p_m2h, *p_mfh;
    cudaGetSymbolAddress((void**)&p_xh,  g_xh);
    cudaGetSymbolAddress((void**)&p_m2h, g_m2h);
    cudaGetSymbolAddress((void**)&p_mfh, g_mfh);

    const int GEMM_SMEM = (128 * 128 + 64 * 128) * (int)sizeof(__half);  // 48KB
    cudaFuncSetAttribute(gemm_hmma_kernel,
                         cudaFuncAttributeMaxDynamicSharedMemorySize, GEMM_SMEM);

    // Preproc: 3 launches
    init_kernel<<<(N_NODES * D / 4 + 255) / 256, 256>>>(x);
    fill_adj_kernel<<<(N_EDGES + 255) / 256, 256>>>(node_idx, hedge_idx);
    pad_adj_kernel<<<(N_NODES + N_HEDGE + 255) / 256, 256>>>();

    const int HGB = (N_HEDGE * 16 + 255) / 256;       // 1563
    const int NGB = (N_NODES / 2 * 16 + 255) / 256;   // 3125

    hedge_gather_kernel<<<HGB, 256>>>(p_xh, p_mfh);
    gemm_hmma_kernel<<<GEMM_TILES, 512, GEMM_SMEM>>>(p_mfh, W1, p_m2h);
    node_gather_kernel<false><<<NGB, 256>>>(p_m2h, b1, nullptr);

    hedge_gather_kernel<<<HGB, 256>>>(p_xh, p_mfh);
    gemm_hmma_kernel<<<GEMM_TILES, 512, GEMM_SMEM>>>(p_mfh, W2, p_m2h);
    node_gather_kernel<false><<<NGB, 256>>>(p_m2h, b2, nullptr);

    hedge_gather_kernel<<<HGB, 256>>>(p_xh, p_mfh);
    gemm_hmma_kernel<<<GEMM_TILES, 512, GEMM_SMEM>>>(p_mfh, W3, p_m2h);
    node_gather_kernel<true><<<NGB, 256>>>(p_m2h, b3, out);
}

// round 17
// speedup vs baseline: 1.3179x; 1.0184x over previous
#include <cuda_runtime.h>
#include <cuda_fp16.h>
#include <math.h>
#include <cstdint>

constexpr int N_NODES = 100000;
constexpr int N_HEDGE = 25000;
constexpr int N_EDGES = 600000;
constexpr int D       = 128;

// Fixed-capacity CSR (clamped; overflow prob ~1e-14).
constexpr int CAP_N = 32;
constexpr int CAP_E = 72;
constexpr int DUMMY_NODE  = N_NODES;
constexpr int DUMMY_HEDGE = N_HEDGE;

constexpr int ROWS_PAD = 25024;            // 391 * 64
constexpr int GEMM_TILES = ROWS_PAD / 64;  // 391

// ---------------------------------------------------------------------------
// Scratch
// ---------------------------------------------------------------------------
__device__ __half g_xh [(N_NODES + 1) * D];   // fp16 node features + zero row
__device__ __half g_m2h[(N_HEDGE + 1) * D];   // fp16 GEMM output + zero row
__device__ __half g_mfh[ROWS_PAD * D];        // fp16 hedge sums (GEMM A)
__device__ int   g_cur_n[N_NODES];
__device__ int   g_cur_e[N_HEDGE];
__device__ __align__(16) int g_adj_e[N_HEDGE * CAP_E + 8];
__device__ __align__(16) int g_adj_n[N_NODES * CAP_N + 8];

// ---------------------------------------------------------------------------
// Preproc A (main stream): cursors + zero rows
// ---------------------------------------------------------------------------
__global__ void cursor_init_kernel() {
    int i = blockIdx.x * blockDim.x + threadIdx.x;
    if (i < N_NODES) g_cur_n[i] = i * CAP_N;
    if (i < N_HEDGE) g_cur_e[i] = i * CAP_E;
    if (i < D) {
        g_xh [(size_t)N_NODES * D + i] = __float2half(0.f);
        g_m2h[(size_t)N_HEDGE * D + i] = __float2half(0.f);
    }
}

// ---------------------------------------------------------------------------
// Preproc B (side stream): fp16 convert of x
// ---------------------------------------------------------------------------
__global__ void convert_x_kernel(const float* __restrict__ x) {
    int i = blockIdx.x * blockDim.x + threadIdx.x;
    if (i >= N_NODES * D / 4) return;
    float4 v = ((const float4*)x)[i];
    __half2 h0 = __floats2half2_rn(v.x, v.y);
    __half2 h1 = __floats2half2_rn(v.z, v.w);
    ((__half2*)g_xh)[i * 2]     = h0;
    ((__half2*)g_xh)[i * 2 + 1] = h1;
}

// ---------------------------------------------------------------------------
// Preproc A2: single-pass adjacency fill (no pad pass; gathers mask tails)
// ---------------------------------------------------------------------------
__global__ void fill_adj_kernel(const int* __restrict__ node_idx,
                                const int* __restrict__ hedge_idx) {
    int e = blockIdx.x * blockDim.x + threadIdx.x;
    if (e >= N_EDGES) return;
    int nd = node_idx[e];
    int h  = hedge_idx[e];
    int p = atomicAdd(&g_cur_e[h], 1);
    if (p < h * CAP_E + CAP_E) g_adj_e[p] = nd;
    int q = atomicAdd(&g_cur_n[nd], 1);
    if (q < nd * CAP_N + CAP_N) g_adj_n[q] = h;
}

// ---------------------------------------------------------------------------
// Half-warp gather helpers (fp16 rows, fp32 accumulation)
// ---------------------------------------------------------------------------
__device__ __forceinline__ void acc_row16(uint4 v, float2* a) {
    float2 f0 = __half22float2(*(const __half2*)&v.x);
    float2 f1 = __half22float2(*(const __half2*)&v.y);
    float2 f2 = __half22float2(*(const __half2*)&v.z);
    float2 f3 = __half22float2(*(const __half2*)&v.w);
    a[0].x += f0.x; a[0].y += f0.y;
    a[1].x += f1.x; a[1].y += f1.y;
    a[2].x += f2.x; a[2].y += f2.y;
    a[3].x += f3.x; a[3].y += f3.y;
}

// Gather with masked tail: full 8-row batches while j+8<=deg, then masked
// int4 batches (invalid slots -> dummy zero row).
__device__ __forceinline__ void gather16(const __half* __restrict__ src,
                                         const int* __restrict__ adj,
                                         int start, int deg, int l16, int dummy,
                                         float2* a) {
    int j = 0;
    for (; j + 8 <= deg; j += 8) {
        int4 iv0 = *(const int4*)(adj + start + j);
        int4 iv1 = *(const int4*)(adj + start + j + 4);
        uint4 r0 = ((const uint4*)(src + (size_t)iv0.x * D))[l16];
        uint4 r1 = ((const uint4*)(src + (size_t)iv0.y * D))[l16];
        uint4 r2 = ((const uint4*)(src + (size_t)iv0.z * D))[l16];
        uint4 r3 = ((const uint4*)(src + (size_t)iv0.w * D))[l16];
        uint4 r4 = ((const uint4*)(src + (size_t)iv1.x * D))[l16];
        uint4 r5 = ((const uint4*)(src + (size_t)iv1.y * D))[l16];
        uint4 r6 = ((const uint4*)(src + (size_t)iv1.z * D))[l16];
        uint4 r7 = ((const uint4*)(src + (size_t)iv1.w * D))[l16];
        acc_row16(r0, a); acc_row16(r1, a); acc_row16(r2, a); acc_row16(r3, a);
        acc_row16(r4, a); acc_row16(r5, a); acc_row16(r6, a); acc_row16(r7, a);
    }
    for (; j < deg; j += 4) {
        int4 iv = *(const int4*)(adj + start + j);   // array has +8 slack
        iv.x = (j + 0 < deg) ? iv.x : dummy;
        iv.y = (j + 1 < deg) ? iv.y : dummy;
        iv.z = (j + 2 < deg) ? iv.z : dummy;
        iv.w = (j + 3 < deg) ? iv.w : dummy;
        uint4 r0 = ((const uint4*)(src + (size_t)iv.x * D))[l16];
        uint4 r1 = ((const uint4*)(src + (size_t)iv.y * D))[l16];
        uint4 r2 = ((const uint4*)(src + (size_t)iv.z * D))[l16];
        uint4 r3 = ((const uint4*)(src + (size_t)iv.w * D))[l16];
        acc_row16(r0, a); acc_row16(r1, a); acc_row16(r2, a); acc_row16(r3, a);
    }
}

// ---------------------------------------------------------------------------
// Hyperedge gather: 1 hedge per half-warp, fp16 output row.
// ---------------------------------------------------------------------------
__global__ void __launch_bounds__(256)
hedge_gather_kernel(const __half* __restrict__ xh, __half* __restrict__ mfh) {
    int lane = threadIdx.x & 31;
    int l16  = lane & 15;
    int h    = ((blockIdx.x * blockDim.x + threadIdx.x) >> 4);
    if (h >= N_HEDGE) return;

    int base = h * CAP_E;
    int deg  = min(g_cur_e[h] - base, CAP_E);

    float2 a[4] = {{0.f,0.f},{0.f,0.f},{0.f,0.f},{0.f,0.f}};
    gather16(xh, g_adj_e, base, deg, l16, DUMMY_NODE, a);

    float s = deg > 0 ? 1.0f / (float)deg : 0.0f;
    __half2 h0 = __floats2half2_rn(a[0].x * s, a[0].y * s);
    __half2 h1 = __floats2half2_rn(a[1].x * s, a[1].y * s);
    __half2 h2 = __floats2half2_rn(a[2].x * s, a[2].y * s);
    __half2 h3 = __floats2half2_rn(a[3].x * s, a[3].y * s);
    uint4 pv;
    pv.x = *(unsigned int*)&h0;
    pv.y = *(unsigned int*)&h1;
    pv.z = *(unsigned int*)&h2;
    pv.w = *(unsigned int*)&h3;
    ((uint4*)(mfh + (size_t)h * D))[l16] = pv;
}

// ---------------------------------------------------------------------------
// HMMA GEMM: m2h[r,:] = fp16( mfh[r,:] @ W ),  64-row tile per block.
// ---------------------------------------------------------------------------
__device__ __forceinline__ uint32_t s2u(const void* p) {
    return (uint32_t)__cvta_generic_to_shared(p);
}

__global__ void __launch_bounds__(512)
gemm_hmma_kernel(const __half* __restrict__ A, const float* __restrict__ W,
                 __half* __restrict__ m2h) {
    extern __shared__ __half smh[];
    __half* Ws = smh;              // 128 x 128
    __half* Xs = smh + 128 * 128;  // 64 x 128
    int t    = threadIdx.x;
    int lane = t & 31;
    int wid  = t >> 5;
    int wm   = wid >> 2;
    int wn   = wid & 3;

    int row0 = blockIdx.x * 64;

    #pragma unroll
    for (int it = 0; it < 4; it++) {
        int ls   = t + it * 512;
        int row  = ls >> 4;
        int c16  = ls & 15;
        int phys = c16 ^ (row & 15);
        float4 f0 = ((const float4*)W)[row * 32 + c16 * 2];
        float4 f1 = ((const float4*)W)[row * 32 + c16 * 2 + 1];
        __half2 q0 = __floats2half2_rn(f0.x, f0.y);
        __half2 q1 = __floats2half2_rn(f0.z, f0.w);
        __half2 q2 = __floats2half2_rn(f1.x, f1.y);
        __half2 q3 = __floats2half2_rn(f1.z, f1.w);
        uint4 pv;
        pv.x = *(unsigned int*)&q0;
        pv.y = *(unsigned int*)&q1;
        pv.z = *(unsigned int*)&q2;
        pv.w = *(unsigned int*)&q3;
        ((uint4*)Ws)[row * 16 + phys] = pv;
    }

    #pragma unroll
    for (int it = 0; it < 2; it++) {
        int ls   = t + it * 512;
        int row  = ls >> 4;
        int c16  = ls & 15;
        int phys = c16 ^ (row & 15);
        uint4 pv = ((const uint4*)(A + (size_t)(row0 + row) * D))[c16];
        ((uint4*)Xs)[row * 16 + phys] = pv;
    }
    __syncthreads();

    float c[4][4];
    #pragma unroll
    for (int j = 0; j < 4; j++)
        #pragma unroll
        for (int q = 0; q < 4; q++) c[j][q] = 0.f;

    int g  = lane >> 3;
    int r8 = lane & 7;

    int arow = wm * 16 + r8 + (g & 1) * 8;
    uint32_t abase = s2u(Xs) + arow * 256;
    int brow_off = r8 + (g & 1) * 8;
    int bq = g >> 1;

    #pragma unroll
    for (int s = 0; s < 8; s++) {
        uint32_t a0, a1, a2, a3;
        {
            int slot = 2 * s + (g >> 1);
            uint32_t addr = abase + ((slot ^ (arow & 15)) << 4);
            asm volatile("ldmatrix.sync.aligned.m8n8.x4.shared.b16 {%0,%1,%2,%3}, [%4];"
                         : "=r"(a0), "=r"(a1), "=r"(a2), "=r"(a3) : "r"(addr));
        }
        uint32_t b[4][2];
        #pragma unroll
        for (int half = 0; half < 2; half++) {
            int brow = 16 * s + brow_off;
            int slot = wn * 4 + half * 2 + bq;
            uint32_t addr = s2u(Ws) + brow * 256 + ((slot ^ (brow & 15)) << 4);
            uint32_t d0, d1, d2, d3;
            asm volatile("ldmatrix.sync.aligned.m8n8.x4.trans.shared.b16 {%0,%1,%2,%3}, [%4];"
                         : "=r"(d0), "=r"(d1), "=r"(d2), "=r"(d3) : "r"(addr));
            b[half * 2][0]     = d0;
            b[half * 2][1]     = d1;
            b[half * 2 + 1][0] = d2;
            b[half * 2 + 1][1] = d3;
        }
        #pragma unroll
        for (int j = 0; j < 4; j++) {
            asm volatile(
                "mma.sync.aligned.m16n8k16.row.col.f32.f16.f16.f32 "
                "{%0,%1,%2,%3}, {%4,%5,%6,%7}, {%8,%9}, {%0,%1,%2,%3};"
                : "+f"(c[j][0]), "+f"(c[j][1]), "+f"(c[j][2]), "+f"(c[j][3])
                : "r"(a0), "r"(a1), "r"(a2), "r"(a3),
                  "r"(b[j][0]), "r"(b[j][1]));
        }
    }

    int tg  = lane >> 2;
    int tig = lane & 3;
    int r_lo = row0 + wm * 16 + tg;
    int r_hi = r_lo + 8;
    int col  = wn * 32 + tig * 2;
    #pragma unroll
    for (int j = 0; j < 4; j++) {
        int cc = col + j * 8;
        if (r_lo < N_HEDGE) {
            __half2 v = __floats2half2_rn(c[j][0], c[j][1]);
            *(__half2*)(m2h + (size_t)r_lo * D + cc) = v;
        }
        if (r_hi < N_HEDGE) {
            __half2 v = __floats2half2_rn(c[j][2], c[j][3]);
            *(__half2*)(m2h + (size_t)r_hi * D + cc) = v;
        }
    }
}

// ---------------------------------------------------------------------------
// Node stage: two nodes per half-warp, interleaved masked loads.
// ---------------------------------------------------------------------------
__device__ __forceinline__ float elu_f(float v) {
    return v > 0.0f ? v : expm1f(v);
}

template <bool LAST>
__global__ void __launch_bounds__(256)
node_gather_kernel(const __half* __restrict__ m2h, const float* __restrict__ bias,
                   float* __restrict__ out) {
    int lane = threadIdx.x & 31;
    int l16  = lane & 15;
    int pid  = ((blockIdx.x * blockDim.x + threadIdx.x) >> 4);
    if (pid >= N_NODES / 2) return;
    int n0 = pid * 2;
    int n1 = n0 + 1;

    int base0 = n0 * CAP_N;
    int base1 = n1 * CAP_N;
    int deg0  = min(g_cur_n[n0] - base0, CAP_N);
    int deg1  = min(g_cur_n[n1] - base1, CAP_N);
    int dmax  = max(deg0, deg1);

    float2 a0[4] = {{0.f,0.f},{0.f,0.f},{0.f,0.f},{0.f,0.f}};
    float2 a1[4] = {{0.f,0.f},{0.f,0.f},{0.f,0.f},{0.f,0.f}};

    for (int j = 0; j < dmax; j += 4) {
        int4 iv0 = *(const int4*)(g_adj_n + base0 + j);
        int4 iv1 = *(const int4*)(g_adj_n + base1 + j);
        iv0.x = (j + 0 < deg0) ? iv0.x : DUMMY_HEDGE;
        iv0.y = (j + 1 < deg0) ? iv0.y : DUMMY_HEDGE;
        iv0.z = (j + 2 < deg0) ? iv0.z : DUMMY_HEDGE;
        iv0.w = (j + 3 < deg0) ? iv0.w : DUMMY_HEDGE;
        iv1.x = (j + 0 < deg1) ? iv1.x : DUMMY_HEDGE;
        iv1.y = (j + 1 < deg1) ? iv1.y : DUMMY_HEDGE;
        iv1.z = (j + 2 < deg1) ? iv1.z : DUMMY_HEDGE;
        iv1.w = (j + 3 < deg1) ? iv1.w : DUMMY_HEDGE;
        uint4 r00 = ((const uint4*)(m2h + (size_t)iv0.x * D))[l16];
        uint4 r01 = ((const uint4*)(m2h + (size_t)iv0.y * D))[l16];
        uint4 r02 = ((const uint4*)(m2h + (size_t)iv0.z * D))[l16];
        uint4 r03 = ((const uint4*)(m2h + (size_t)iv0.w * D))[l16];
        uint4 r10 = ((const uint4*)(m2h + (size_t)iv1.x * D))[l16];
        uint4 r11 = ((const uint4*)(m2h + (size_t)iv1.y * D))[l16];
        uint4 r12 = ((const uint4*)(m2h + (size_t)iv1.z * D))[l16];
        uint4 r13 = ((const uint4*)(m2h + (size_t)iv1.w * D))[l16];
        acc_row16(r00, a0); acc_row16(r01, a0);
        acc_row16(r02, a0); acc_row16(r03, a0);
        acc_row16(r10, a1); acc_row16(r11, a1);
        acc_row16(r12, a1); acc_row16(r13, a1);
    }

    float4 b0 = ((const float4*)bias)[2 * l16];
    float4 b1 = ((const float4*)bias)[2 * l16 + 1];

    #pragma unroll
    for (int r = 0; r < 2; r++) {
        float2* a  = r ? a1 : a0;
        int     gw = r ? n1 : n0;
        int    deg = r ? deg1 : deg0;
        float s = deg > 0 ? 1.0f / (float)deg : 0.0f;
        float v0 = elu_f(fmaf(a[0].x, s, b0.x));
        float v1 = elu_f(fmaf(a[0].y, s, b0.y));
        float v2 = elu_f(fmaf(a[1].x, s, b0.z));
        float v3 = elu_f(fmaf(a[1].y, s, b0.w));
        float v4 = elu_f(fmaf(a[2].x, s, b1.x));
        float v5 = elu_f(fmaf(a[2].y, s, b1.y));
        float v6 = elu_f(fmaf(a[3].x, s, b1.z));
        float v7 = elu_f(fmaf(a[3].y, s, b1.w));
        if (LAST) {
            float4* orow = (float4*)(out + (size_t)gw * D);
            orow[2 * l16]     = make_float4(v0, v1, v2, v3);
            orow[2 * l16 + 1] = make_float4(v4, v5, v6, v7);
        } else {
            __half2 h0 = __floats2half2_rn(v0, v1);
            __half2 h1 = __floats2half2_rn(v2, v3);
            __half2 h2 = __floats2half2_rn(v4, v5);
            __half2 h3 = __floats2half2_rn(v6, v7);
            uint4 pv;
            pv.x = *(unsigned int*)&h0;
            pv.y = *(unsigned int*)&h1;
            pv.z = *(unsigned int*)&h2;
            pv.w = *(unsigned int*)&h3;
            ((uint4*)(g_xh + (size_t)gw * D))[l16] = pv;
        }
    }
}

// ---------------------------------------------------------------------------
// Launch: fork convert_x onto a side stream, overlapped with adjacency build.
// Stream/events created once (outside capture); same captured ops every call.
// ---------------------------------------------------------------------------
extern "C" void kernel_launch(void* const* d_in, const int* in_sizes, int n_in,
                              void* d_out, int out_size) {
    const float* x  = (const float*)d_in[0];
    const float* W1 = (const float*)d_in[1];
    const float* b1 = (const float*)d_in[2];
    const float* W2 = (const float*)d_in[3];
    const float* b2 = (const float*)d_in[4];
    const float* W3 = (const float*)d_in[5];
    const float* b3 = (const float*)d_in[6];
    const int* node_idx  = (const int*)d_in[7];
    const int* hedge_idx = (const int*)d_in[8];
    float* out = (float*)d_out;

    __half *p_xh, *p_m2h, *p_mfh;
    cudaGetSymbolAddress((void**)&p_xh,  g_xh);
    cudaGetSymbolAddress((void**)&p_m2h, g_m2h);
    cudaGetSymbolAddress((void**)&p_mfh, g_mfh);

    static cudaStream_t sB = nullptr;
    static cudaEvent_t evFork = nullptr, evJoin = nullptr;
    if (sB == nullptr) {
        cudaStreamCreate(&sB);
        cudaEventCreateWithFlags(&evFork, cudaEventDisableTiming);
        cudaEventCreateWithFlags(&evJoin, cudaEventDisableTiming);
    }

    const int GEMM_SMEM = (128 * 128 + 64 * 128) * (int)sizeof(__half);  // 48KB
    cudaFuncSetAttribute(gemm_hmma_kernel,
                         cudaFuncAttributeMaxDynamicSharedMemorySize, GEMM_SMEM);

    // Fork: convert_x on side stream, adjacency build on main stream.
    cudaEventRecord(evFork, 0);
    cudaStreamWaitEvent(sB, evFork, 0);
    convert_x_kernel<<<(N_NODES * D / 4 + 255) / 256, 256, 0, sB>>>(x);
    cudaEventRecord(evJoin, sB);

    cursor_init_kernel<<<(N_NODES + 255) / 256, 256>>>();
    fill_adj_kernel<<<(N_EDGES + 255) / 256, 256>>>(node_idx, hedge_idx);

    // Join before first consumer of g_xh.
    cudaStreamWaitEvent(0, evJoin, 0);

    const int HGB = (N_HEDGE * 16 + 255) / 256;       // 1563
    const int NGB = (N_NODES / 2 * 16 + 255) / 256;   // 3125

    hedge_gather_kernel<<<HGB, 256>>>(p_xh, p_mfh);
    gemm_hmma_kernel<<<GEMM_TILES, 512, GEMM_SMEM>>>(p_mfh, W1, p_m2h);
    node_gather_kernel<false><<<NGB, 256>>>(p_m2h, b1, nullptr);

    hedge_gather_kernel<<<HGB, 256>>>(p_xh, p_mfh);
    gemm_hmma_kernel<<<GEMM_TILES, 512, GEMM_SMEM>>>(p_mfh, W2, p_m2h);
    node_gather_kernel<false><<<NGB, 256>>>(p_m2h, b2, nullptr);

    hedge_gather_kernel<<<HGB, 256>>>(p_xh, p_mfh);
    gemm_hmma_kernel<<<GEMM_TILES, 512, GEMM_SMEM>>>(p_mfh, W3, p_m2h);
    node_gather_kernel<true><<<NGB, 256>>>(p_m2h, b3, out);
}